// round 2
// baseline (speedup 1.0000x reference)
#include <cuda_runtime.h>
#include <cuda_fp16.h>
#include <mma.h>

using namespace nvcuda;

#define DEV_INLINE __device__ __forceinline__

// Problem constants
constexpr int B_ = 4, T_ = 2048, C_ = 2048, H_ = 16, HK_ = 4, D_ = 128, WIN_ = 1024;
constexpr int BT  = B_ * T_;    // 8192
constexpr int HD  = H_ * D_;    // 2048
constexpr int HKD = HK_ * D_;   // 512
constexpr float EPS = 1.1920928955078125e-07f;   // fp32 machine eps (matches jnp.finfo)
constexpr float ATT_SCALE = 0.08838834764831845f; // 1/sqrt(128)

// ---------------------------------------------------------------------------
// Scratch (device globals: allowed, no cudaMalloc)
// ---------------------------------------------------------------------------
__device__ __half g_xq_hi[BT * C_], g_xq_lo[BT * C_];   // alpha_q*x + beta_q*rmsnorm(x0)
__device__ __half g_xk_hi[BT * C_], g_xk_lo[BT * C_];   // alpha_k*x + beta_k*rmsnorm(x0)
__device__ __half g_x_hi [BT * C_], g_x_lo [BT * C_];   // x        (for v_init GEMM)
__device__ __half g_xn_hi[BT * C_], g_xn_lo[BT * C_];   // rmsnorm(x0) (for cvx GEMM)

__device__ __half g_Wq_hi[HD * C_],  g_Wq_lo[HD * C_];
__device__ __half g_Wk_hi[HKD * C_], g_Wk_lo[HKD * C_];
__device__ __half g_Wv_hi[HKD * C_], g_Wv_lo[HKD * C_];
__device__ __half g_Wp_hi[C_ * HD],  g_Wp_lo[C_ * HD];

__device__ float g_Q  [BT * HD];    // pre-rope Q
__device__ float g_K  [BT * HKD];   // pre-rope K
__device__ float g_cvx[BT * HKD];   // rmsnorm(x0) @ Wv^T

__device__ __half g_qa_hi[BT * HD],  g_qa_lo[BT * HD];   // post rope+rmsnorm*1.2
__device__ __half g_ka_hi[BT * HKD], g_ka_lo[BT * HKD];
__device__ __half g_va_hi[BT * HKD], g_va_lo[BT * HKD];  // mixed v
__device__ __half g_att_hi[BT * HD], g_att_lo[BT * HD];  // attention output

DEV_INLINE void split_store(float v, __half* hi, __half* lo, size_t idx) {
    __half h = __float2half_rn(v);
    hi[idx] = h;
    lo[idx] = __float2half_rn(v - __half2float(h));
}

// ---------------------------------------------------------------------------
// Weight fp32 -> (hi, lo) fp16 split
// ---------------------------------------------------------------------------
DEV_INLINE void conv_body(const float* __restrict__ w, __half* hi, __half* lo, int n) {
    int i = blockIdx.x * 256 + threadIdx.x;
    if (i < n) split_store(w[i], hi, lo, i);
}
__global__ void conv_wq(const float* __restrict__ w) { conv_body(w, g_Wq_hi, g_Wq_lo, HD * C_); }
__global__ void conv_wk(const float* __restrict__ w) { conv_body(w, g_Wk_hi, g_Wk_lo, HKD * C_); }
__global__ void conv_wv(const float* __restrict__ w) { conv_body(w, g_Wv_hi, g_Wv_lo, HKD * C_); }
__global__ void conv_wp(const float* __restrict__ w) { conv_body(w, g_Wp_hi, g_Wp_lo, C_ * HD); }

// ---------------------------------------------------------------------------
// Fused rmsnorm(x0) + linear mix:  xq = aq*x + bq*x0n ; xk = ak*x + bk*x0n
// one block (256 thr) per row of 2048
// ---------------------------------------------------------------------------
__global__ void __launch_bounds__(256) mix_kernel(
    const float* __restrict__ x, const float* __restrict__ x0,
    const float* __restrict__ aq, const float* __restrict__ bq,
    const float* __restrict__ ak, const float* __restrict__ bk)
{
    __shared__ float sred[8];
    const int row = blockIdx.x;
    const int tid = threadIdx.x;
    const size_t base = (size_t)row * C_;

    const float4* x0v = (const float4*)(x0 + base);
    const float4* xv  = (const float4*)(x + base);
    float4 u0 = x0v[tid], u1 = x0v[tid + 256];
    float ssq = u0.x*u0.x + u0.y*u0.y + u0.z*u0.z + u0.w*u0.w
              + u1.x*u1.x + u1.y*u1.y + u1.z*u1.z + u1.w*u1.w;
#pragma unroll
    for (int o = 16; o > 0; o >>= 1) ssq += __shfl_xor_sync(0xffffffffu, ssq, o);
    if ((tid & 31) == 0) sred[tid >> 5] = ssq;
    __syncthreads();
    float tot = 0.f;
#pragma unroll
    for (int i = 0; i < 8; i++) tot += sred[i];
    const float rinv = rsqrtf(tot / (float)C_ + EPS);

    const float aqv = *aq, bqv = *bq, akv = *ak, bkv = *bk;
    float4 v0 = xv[tid], v1 = xv[tid + 256];

    float xs[8]  = {v0.x, v0.y, v0.z, v0.w, v1.x, v1.y, v1.z, v1.w};
    float x0s[8] = {u0.x, u0.y, u0.z, u0.w, u1.x, u1.y, u1.z, u1.w};
#pragma unroll
    for (int c = 0; c < 8; c++) {
        size_t e = base + (size_t)((c < 4 ? tid : tid + 256) * 4 + (c & 3));
        float xvv = xs[c];
        float xnn = x0s[c] * rinv;
        split_store(xvv, g_x_hi,  g_x_lo,  e);
        split_store(xnn, g_xn_hi, g_xn_lo, e);
        split_store(aqv * xvv + bqv * xnn, g_xq_hi, g_xq_lo, e);
        split_store(akv * xvv + bkv * xnn, g_xk_hi, g_xk_lo, e);
    }
}

// ---------------------------------------------------------------------------
// Split-fp16 TN GEMM:  C[M,N] = A[M,K] @ B[N,K]^T, K=2048, M=8192, fp32 out
// A = Ahi + Alo, B = Bhi + Blo; accumulate hihi + hilo + lohi (3 mma passes)
// Block tile 128x128x32, 8 warps (2x4), warp tile 64x32 (4x2 wmma frags)
// ---------------------------------------------------------------------------
DEV_INLINE void gemm_body(const __half* __restrict__ Ahi, const __half* __restrict__ Alo,
                          const __half* __restrict__ Bhi, const __half* __restrict__ Blo,
                          float* __restrict__ Cg, int N)
{
    __shared__ __half Ash[128 * 40], Asl[128 * 40], Bsh[128 * 40], Bsl[128 * 40];
    const int tid = threadIdx.x;
    const int wid = tid >> 5;
    const int wm = wid >> 2, wn = wid & 3;
    const int bm = blockIdx.y, bn = blockIdx.x;

    wmma::fragment<wmma::accumulator, 16, 16, 16, float> acc[4][2];
#pragma unroll
    for (int i = 0; i < 4; i++)
#pragma unroll
        for (int j = 0; j < 2; j++) wmma::fill_fragment(acc[i][j], 0.f);

    const int r0 = tid >> 2;
    const int c0 = (tid & 3) * 8;
    const size_t aoff0 = (size_t)(bm * 128 + r0) * 2048 + c0;
    const size_t aoff1 = aoff0 + (size_t)64 * 2048;
    const size_t boff0 = (size_t)(bn * 128 + r0) * 2048 + c0;
    const size_t boff1 = boff0 + (size_t)64 * 2048;
    const int s0 = r0 * 40 + c0;
    const int s1 = (r0 + 64) * 40 + c0;

    float4 pAh0, pAh1, pAl0, pAl1, pBh0, pBh1, pBl0, pBl1;
    pAh0 = *(const float4*)(Ahi + aoff0); pAh1 = *(const float4*)(Ahi + aoff1);
    pAl0 = *(const float4*)(Alo + aoff0); pAl1 = *(const float4*)(Alo + aoff1);
    pBh0 = *(const float4*)(Bhi + boff0); pBh1 = *(const float4*)(Bhi + boff1);
    pBl0 = *(const float4*)(Blo + boff0); pBl1 = *(const float4*)(Blo + boff1);
    *(float4*)(Ash + s0) = pAh0; *(float4*)(Ash + s1) = pAh1;
    *(float4*)(Asl + s0) = pAl0; *(float4*)(Asl + s1) = pAl1;
    *(float4*)(Bsh + s0) = pBh0; *(float4*)(Bsh + s1) = pBh1;
    *(float4*)(Bsl + s0) = pBl0; *(float4*)(Bsl + s1) = pBl1;
    __syncthreads();

    for (int kt = 0; kt < 64; ++kt) {
        if (kt < 63) {
            const int kn = (kt + 1) * 32;
            pAh0 = *(const float4*)(Ahi + aoff0 + kn); pAh1 = *(const float4*)(Ahi + aoff1 + kn);
            pAl0 = *(const float4*)(Alo + aoff0 + kn); pAl1 = *(const float4*)(Alo + aoff1 + kn);
            pBh0 = *(const float4*)(Bhi + boff0 + kn); pBh1 = *(const float4*)(Bhi + boff1 + kn);
            pBl0 = *(const float4*)(Blo + boff0 + kn); pBl1 = *(const float4*)(Blo + boff1 + kn);
        }
#pragma unroll
        for (int kk = 0; kk < 32; kk += 16) {
            wmma::fragment<wmma::matrix_a, 16, 16, 16, __half, wmma::row_major> ah[4], al[4];
            wmma::fragment<wmma::matrix_b, 16, 16, 16, __half, wmma::col_major> bh[2], bl[2];
#pragma unroll
            for (int i = 0; i < 4; i++) {
                wmma::load_matrix_sync(ah[i], Ash + (wm * 64 + i * 16) * 40 + kk, 40);
                wmma::load_matrix_sync(al[i], Asl + (wm * 64 + i * 16) * 40 + kk, 40);
            }
#pragma unroll
            for (int j = 0; j < 2; j++) {
                wmma::load_matrix_sync(bh[j], Bsh + (wn * 32 + j * 16) * 40 + kk, 40);
                wmma::load_matrix_sync(bl[j], Bsl + (wn * 32 + j * 16) * 40 + kk, 40);
            }
#pragma unroll
            for (int i = 0; i < 4; i++)
#pragma unroll
                for (int j = 0; j < 2; j++) {
                    wmma::mma_sync(acc[i][j], ah[i], bh[j], acc[i][j]);
                    wmma::mma_sync(acc[i][j], ah[i], bl[j], acc[i][j]);
                    wmma::mma_sync(acc[i][j], al[i], bh[j], acc[i][j]);
                }
        }
        __syncthreads();
        if (kt < 63) {
            *(float4*)(Ash + s0) = pAh0; *(float4*)(Ash + s1) = pAh1;
            *(float4*)(Asl + s0) = pAl0; *(float4*)(Asl + s1) = pAl1;
            *(float4*)(Bsh + s0) = pBh0; *(float4*)(Bsh + s1) = pBh1;
            *(float4*)(Bsl + s0) = pBl0; *(float4*)(Bsl + s1) = pBl1;
        }
        __syncthreads();
    }

#pragma unroll
    for (int i = 0; i < 4; i++)
#pragma unroll
        for (int j = 0; j < 2; j++) {
            const int row = bm * 128 + wm * 64 + i * 16;
            const int col = bn * 128 + wn * 32 + j * 16;
            wmma::store_matrix_sync(Cg + (size_t)row * N + col, acc[i][j], N, wmma::mem_row_major);
        }
}

__global__ void __launch_bounds__(256) gemm_q_kernel()              { gemm_body(g_xq_hi, g_xq_lo, g_Wq_hi, g_Wq_lo, g_Q, 2048); }
__global__ void __launch_bounds__(256) gemm_k_kernel()              { gemm_body(g_xk_hi, g_xk_lo, g_Wk_hi, g_Wk_lo, g_K, 512); }
__global__ void __launch_bounds__(256) gemm_vinit_kernel(float* o)  { gemm_body(g_x_hi,  g_x_lo,  g_Wv_hi, g_Wv_lo, o, 512); }
__global__ void __launch_bounds__(256) gemm_cvx_kernel()            { gemm_body(g_xn_hi, g_xn_lo, g_Wv_hi, g_Wv_lo, g_cvx, 512); }
__global__ void __launch_bounds__(256) gemm_proj_kernel(float* o)   { gemm_body(g_att_hi, g_att_lo, g_Wp_hi, g_Wp_lo, o, 2048); }

// ---------------------------------------------------------------------------
// RoPE + rmsnorm * 1.2, one warp per (b,t,head) row of 128
// ---------------------------------------------------------------------------
DEV_INLINE void rope_body(const float* __restrict__ inp, __half* __restrict__ ohi,
                          __half* __restrict__ olo, const float* __restrict__ cosb,
                          const float* __restrict__ sinb, int nh)
{
    const int wg = blockIdx.x * 8 + (threadIdx.x >> 5);
    const int lane = threadIdx.x & 31;
    const int t = (wg / nh) % T_;
    const size_t base = (size_t)wg * 128;

    float x1a = inp[base + lane];
    float x1b = inp[base + 32 + lane];
    float x2a = inp[base + 64 + lane];
    float x2b = inp[base + 96 + lane];
    float ca = cosb[t * 64 + lane], cb = cosb[t * 64 + 32 + lane];
    float sa = sinb[t * 64 + lane], sb = sinb[t * 64 + 32 + lane];

    float o1a =  x1a * ca + x2a * sa;
    float o1b =  x1b * cb + x2b * sb;
    float o2a = -x1a * sa + x2a * ca;
    float o2b = -x1b * sb + x2b * cb;

    float ssq = o1a*o1a + o1b*o1b + o2a*o2a + o2b*o2b;
#pragma unroll
    for (int o = 16; o > 0; o >>= 1) ssq += __shfl_xor_sync(0xffffffffu, ssq, o);
    float sc = rsqrtf(ssq / 128.f + EPS) * 1.2f;

    split_store(o1a * sc, ohi, olo, base + lane);
    split_store(o1b * sc, ohi, olo, base + 32 + lane);
    split_store(o2a * sc, ohi, olo, base + 64 + lane);
    split_store(o2b * sc, ohi, olo, base + 96 + lane);
}
__global__ void __launch_bounds__(256) rope_q_kernel(const float* c, const float* s) { rope_body(g_Q, g_qa_hi, g_qa_lo, c, s, H_); }
__global__ void __launch_bounds__(256) rope_k_kernel(const float* c, const float* s) { rope_body(g_K, g_ka_hi, g_ka_lo, c, s, HK_); }

// ---------------------------------------------------------------------------
// v = alpha_v * v_init + beta_v * cvx  ->  split halves for attention
// ---------------------------------------------------------------------------
__global__ void __launch_bounds__(256) vcomb_kernel(const float* __restrict__ vinit,
                                                    const float* __restrict__ av,
                                                    const float* __restrict__ bv)
{
    int i = blockIdx.x * 256 + threadIdx.x;  // n = BT*HKD exact
    float v = (*av) * vinit[i] + (*bv) * g_cvx[i];
    split_store(v, g_va_hi, g_va_lo, i);
}

// ---------------------------------------------------------------------------
// Windowed causal flash attention. CTA = (64 queries, one (b,h)).
// Split QK^T (3 mma passes), online softmax with smem fp32 accumulator,
// P @ (Vhi + Vlo). 128 threads (4 warps). Dynamic smem 166912 B.
// ---------------------------------------------------------------------------
constexpr int ATT_SMEM = 166912;

__global__ void __launch_bounds__(128) attn_kernel()
{
    extern __shared__ char smraw[];
    __half* Qh = (__half*)(smraw);
    __half* Ql = (__half*)(smraw + 17408);
    __half* Kh = (__half*)(smraw + 34816);
    __half* Kl = (__half*)(smraw + 52224);
    __half* Vh = (__half*)(smraw + 69632);
    __half* Vl = (__half*)(smraw + 87040);
    float*  O  = (float*)(smraw + 104448);   // 64 x 136
    float*  S  = (float*)(smraw + 139264);   // 64 x 72
    __half* P  = (__half*)(smraw + 157696);  // 64 x 72

    const int tid = threadIdx.x;
    const int warp = tid >> 5;
    const int b = blockIdx.z, h = blockIdx.y;
    const int q0 = blockIdx.x * 64;
    const int hk = h >> 2;
    const int m0 = warp * 16;

    // load Q tile (hi/lo)
#pragma unroll
    for (int tc = 0; tc < 8; ++tc) {
        int chunk = tid + tc * 128;
        int r = chunk >> 4;
        int c = (chunk & 15) * 8;
        size_t g = (size_t)(b * T_ + q0 + r) * 2048 + h * 128 + c;
        *(float4*)(Qh + r * 136 + c) = *(const float4*)(g_qa_hi + g);
        *(float4*)(Ql + r * 136 + c) = *(const float4*)(g_qa_lo + g);
    }
    for (int i = tid; i < 64 * 136; i += 128) O[i] = 0.f;
    float m_r = -1e30f, l_r = 0.f;
    __syncthreads();

    const int kb0 = max(0, q0 - WIN_) >> 6;
    const int kb1 = q0 >> 6;
    for (int kb = kb0; kb <= kb1; ++kb) {
        const int k0 = kb * 64;
#pragma unroll
        for (int tc = 0; tc < 8; ++tc) {
            int chunk = tid + tc * 128;
            int r = chunk >> 4;
            int c = (chunk & 15) * 8;
            size_t g = (size_t)(b * T_ + k0 + r) * 512 + hk * 128 + c;
            *(float4*)(Kh + r * 136 + c) = *(const float4*)(g_ka_hi + g);
            *(float4*)(Kl + r * 136 + c) = *(const float4*)(g_ka_lo + g);
            *(float4*)(Vh + r * 136 + c) = *(const float4*)(g_va_hi + g);
            *(float4*)(Vl + r * 136 + c) = *(const float4*)(g_va_lo + g);
        }
        __syncthreads();

        // S = Q K^T  (split, 3 passes)
        wmma::fragment<wmma::accumulator, 16, 16, 16, float> sacc[4];
#pragma unroll
        for (int j = 0; j < 4; j++) wmma::fill_fragment(sacc[j], 0.f);
#pragma unroll
        for (int kk = 0; kk < 8; ++kk) {
            wmma::fragment<wmma::matrix_a, 16, 16, 16, __half, wmma::row_major> ah, al;
            wmma::load_matrix_sync(ah, Qh + m0 * 136 + kk * 16, 136);
            wmma::load_matrix_sync(al, Ql + m0 * 136 + kk * 16, 136);
#pragma unroll
            for (int j = 0; j < 4; j++) {
                wmma::fragment<wmma::matrix_b, 16, 16, 16, __half, wmma::col_major> bh, bl;
                wmma::load_matrix_sync(bh, Kh + (j * 16) * 136 + kk * 16, 136);
                wmma::load_matrix_sync(bl, Kl + (j * 16) * 136 + kk * 16, 136);
                wmma::mma_sync(sacc[j], ah, bh, sacc[j]);
                wmma::mma_sync(sacc[j], ah, bl, sacc[j]);
                wmma::mma_sync(sacc[j], al, bh, sacc[j]);
            }
        }
#pragma unroll
        for (int j = 0; j < 4; j++)
            wmma::store_matrix_sync(S + m0 * 72 + j * 16, sacc[j], 72, wmma::mem_row_major);
        __syncthreads();

        // online softmax (thread r owns row r)
        if (tid < 64) {
            const int i_q = q0 + tid;
            float* Srow = S + tid * 72;
            float mx = -1e30f;
#pragma unroll 8
            for (int c = 0; c < 64; c++) {
                int j = k0 + c;
                float s = Srow[c] * ATT_SCALE;
                bool valid = (j <= i_q) && (i_q - j <= WIN_);
                s = valid ? s : -1e30f;
                Srow[c] = s;
                mx = fmaxf(mx, s);
            }
            float m_new = fmaxf(m_r, mx);
            float alpha = __expf(m_r - m_new);
            float lsum = 0.f;
            __half* Prow = P + tid * 72;
#pragma unroll 8
            for (int c = 0; c < 64; c++) {
                float p = __expf(Srow[c] - m_new);
                lsum += p;
                Prow[c] = __float2half_rn(p);
            }
            l_r = l_r * alpha + lsum;
            m_r = m_new;
            float* Orow = O + tid * 136;
#pragma unroll 8
            for (int c = 0; c < 128; c++) Orow[c] *= alpha;
        }
        __syncthreads();

        // O += P @ (Vhi + Vlo)
#pragma unroll
        for (int j = 0; j < 8; j++) {
            wmma::fragment<wmma::accumulator, 16, 16, 16, float> cfr;
            wmma::load_matrix_sync(cfr, O + m0 * 136 + j * 16, 136, wmma::mem_row_major);
#pragma unroll
            for (int kk = 0; kk < 4; kk++) {
                wmma::fragment<wmma::matrix_a, 16, 16, 16, __half, wmma::row_major> pa;
                wmma::load_matrix_sync(pa, P + m0 * 72 + kk * 16, 72);
                wmma::fragment<wmma::matrix_b, 16, 16, 16, __half, wmma::row_major> vb;
                wmma::load_matrix_sync(vb, Vh + (kk * 16) * 136 + j * 16, 136);
                wmma::mma_sync(cfr, pa, vb, cfr);
                wmma::load_matrix_sync(vb, Vl + (kk * 16) * 136 + j * 16, 136);
                wmma::mma_sync(cfr, pa, vb, cfr);
            }
            wmma::store_matrix_sync(O + m0 * 136 + j * 16, cfr, 136, wmma::mem_row_major);
        }
        __syncthreads();
    }

    // normalize + split-store attention output
    if (tid < 64) {
        const float inv_l = 1.f / l_r;
        float* Orow = O + tid * 136;
        size_t g = (size_t)(b * T_ + q0 + tid) * 2048 + h * 128;
        for (int c = 0; c < 128; c++) {
            float v = Orow[c] * inv_l;
            __half hi = __float2half_rn(v);
            g_att_hi[g + c] = hi;
            g_att_lo[g + c] = __float2half_rn(v - __half2float(hi));
        }
    }
}

// ---------------------------------------------------------------------------
// Launcher
// ---------------------------------------------------------------------------
extern "C" void kernel_launch(void* const* d_in, const int* in_sizes, int n_in,
                              void* d_out, int out_size)
{
    const float* x    = (const float*)d_in[0];
    const float* x0   = (const float*)d_in[1];
    // d_in[2] = ve : all zeros and unused by the reference
    const float* cosb = (const float*)d_in[3];
    const float* sinb = (const float*)d_in[4];
    const float* Wq   = (const float*)d_in[5];
    const float* Wk   = (const float*)d_in[6];
    const float* Wv   = (const float*)d_in[7];
    const float* Wp   = (const float*)d_in[8];
    const float* aq   = (const float*)d_in[9];
    const float* bq   = (const float*)d_in[10];
    const float* ak   = (const float*)d_in[11];
    const float* bk   = (const float*)d_in[12];
    const float* av   = (const float*)d_in[13];
    const float* bv   = (const float*)d_in[14];

    float* outY = (float*)d_out;                       // (B,T,C)
    float* outV = outY + (size_t)BT * C_;              // (B,T,HK,D)

    cudaFuncSetAttribute(attn_kernel, cudaFuncAttributeMaxDynamicSharedMemorySize, ATT_SMEM);

    conv_wq<<<(HD * C_) / 256, 256>>>(Wq);
    conv_wk<<<(HKD * C_) / 256, 256>>>(Wk);
    conv_wv<<<(HKD * C_) / 256, 256>>>(Wv);
    conv_wp<<<(C_ * HD) / 256, 256>>>(Wp);

    mix_kernel<<<BT, 256>>>(x, x0, aq, bq, ak, bk);

    gemm_q_kernel    <<<dim3(16, 64), 256>>>();
    gemm_k_kernel    <<<dim3(4, 64), 256>>>();
    gemm_vinit_kernel<<<dim3(4, 64), 256>>>(outV);
    gemm_cvx_kernel  <<<dim3(4, 64), 256>>>();

    // one warp per head-row: BT*H rows for Q, BT*HK rows for K; 8 warps/block
    rope_q_kernel<<<(BT * H_) / 8, 256>>>(cosb, sinb);
    rope_k_kernel<<<(BT * HK_) / 8, 256>>>(cosb, sinb);

    vcomb_kernel<<<(BT * HKD) / 256, 256>>>(outV, av, bv);

    attn_kernel<<<dim3(T_ / 64, H_, B_), 128, ATT_SMEM>>>();

    gemm_proj_kernel<<<dim3(16, 64), 256>>>(outY);
}

// round 4
// speedup vs baseline: 1.5136x; 1.5136x over previous
#include <cuda_runtime.h>
#include <cuda_fp16.h>
#include <mma.h>

using namespace nvcuda;

#define DEV_INLINE __device__ __forceinline__

// Problem constants
constexpr int B_ = 4, T_ = 2048, C_ = 2048, H_ = 16, HK_ = 4, D_ = 128, WIN_ = 1024;
constexpr int BT  = B_ * T_;    // 8192
constexpr int HD  = H_ * D_;    // 2048
constexpr int HKD = HK_ * D_;   // 512
constexpr float EPS = 1.1920928955078125e-07f;
constexpr float ATT_SCALE = 0.08838834764831845f; // 1/sqrt(128)

// ---------------------------------------------------------------------------
// Scratch (device globals)
// ---------------------------------------------------------------------------
__device__ __half g_xq[BT * C_];   // alpha_q*x + beta_q*rmsnorm(x0)
__device__ __half g_xk[BT * C_];   // alpha_k*x + beta_k*rmsnorm(x0)
__device__ __half g_x [BT * C_];   // x          (v_init GEMM A)
__device__ __half g_xn[BT * C_];   // rmsnorm(x0) (cvx GEMM A)

__device__ __half g_Wq_hi[HD * C_],  g_Wq_lo[HD * C_];
__device__ __half g_Wk_hi[HKD * C_], g_Wk_lo[HKD * C_];
__device__ __half g_Wv_hi[HKD * C_], g_Wv_lo[HKD * C_];
__device__ __half g_Wp_hi[C_ * HD],  g_Wp_lo[C_ * HD];

__device__ float g_Q  [BT * HD];    // pre-rope Q
__device__ float g_K  [BT * HKD];   // pre-rope K
__device__ float g_cvx[BT * HKD];   // rmsnorm(x0) @ Wv^T

__device__ __half g_qa [BT * HD];   // post rope+rmsnorm*1.2
__device__ __half g_ka [BT * HKD];
__device__ __half g_va [BT * HKD];  // mixed v
__device__ __half g_att[BT * HD];   // attention output

DEV_INLINE void split_store(float v, __half* hi, __half* lo, size_t idx) {
    __half h = __float2half_rn(v);
    hi[idx] = h;
    lo[idx] = __float2half_rn(v - __half2float(h));
}

// ---------------------------------------------------------------------------
// Weight fp32 -> (hi, lo) fp16 split
// ---------------------------------------------------------------------------
DEV_INLINE void conv_body(const float* __restrict__ w, __half* hi, __half* lo, int n) {
    int i = blockIdx.x * 256 + threadIdx.x;
    if (i < n) split_store(w[i], hi, lo, i);
}
__global__ void conv_wq(const float* __restrict__ w) { conv_body(w, g_Wq_hi, g_Wq_lo, HD * C_); }
__global__ void conv_wk(const float* __restrict__ w) { conv_body(w, g_Wk_hi, g_Wk_lo, HKD * C_); }
__global__ void conv_wv(const float* __restrict__ w) { conv_body(w, g_Wv_hi, g_Wv_lo, HKD * C_); }
__global__ void conv_wp(const float* __restrict__ w) { conv_body(w, g_Wp_hi, g_Wp_lo, C_ * HD); }

// ---------------------------------------------------------------------------
// Fused rmsnorm(x0) + linear mix, fp16 outputs
// ---------------------------------------------------------------------------
__global__ void __launch_bounds__(256) mix_kernel(
    const float* __restrict__ x, const float* __restrict__ x0,
    const float* __restrict__ aq, const float* __restrict__ bq,
    const float* __restrict__ ak, const float* __restrict__ bk)
{
    __shared__ float sred[8];
    const int row = blockIdx.x;
    const int tid = threadIdx.x;
    const size_t base = (size_t)row * C_;

    const float4* x0v = (const float4*)(x0 + base);
    const float4* xv  = (const float4*)(x + base);
    float4 u0 = x0v[tid], u1 = x0v[tid + 256];
    float ssq = u0.x*u0.x + u0.y*u0.y + u0.z*u0.z + u0.w*u0.w
              + u1.x*u1.x + u1.y*u1.y + u1.z*u1.z + u1.w*u1.w;
#pragma unroll
    for (int o = 16; o > 0; o >>= 1) ssq += __shfl_xor_sync(0xffffffffu, ssq, o);
    if ((tid & 31) == 0) sred[tid >> 5] = ssq;
    __syncthreads();
    float tot = 0.f;
#pragma unroll
    for (int i = 0; i < 8; i++) tot += sred[i];
    const float rinv = rsqrtf(tot / (float)C_ + EPS);

    const float aqv = *aq, bqv = *bq, akv = *ak, bkv = *bk;
    float4 v0 = xv[tid], v1 = xv[tid + 256];

    float xs[8]  = {v0.x, v0.y, v0.z, v0.w, v1.x, v1.y, v1.z, v1.w};
    float x0s[8] = {u0.x, u0.y, u0.z, u0.w, u1.x, u1.y, u1.z, u1.w};
#pragma unroll
    for (int c = 0; c < 8; c++) {
        size_t e = base + (size_t)((c < 4 ? tid : tid + 256) * 4 + (c & 3));
        float xvv = xs[c];
        float xnn = x0s[c] * rinv;
        g_x [e] = __float2half_rn(xvv);
        g_xn[e] = __float2half_rn(xnn);
        g_xq[e] = __float2half_rn(aqv * xvv + bqv * xnn);
        g_xk[e] = __float2half_rn(akv * xvv + bkv * xnn);
    }
}

// ---------------------------------------------------------------------------
// fp16 TN GEMM with weight compensation: C = A @ (Bhi + Blo)^T
// Block tile 128x128x32, 8 warps (2x4), warp tile 64x32, 2 mma passes
// ---------------------------------------------------------------------------
DEV_INLINE void gemm_body(const __half* __restrict__ A,
                          const __half* __restrict__ Bhi, const __half* __restrict__ Blo,
                          float* __restrict__ Cg, int N)
{
    __shared__ __half Ash[128 * 40], Bsh[128 * 40], Bsl[128 * 40];
    const int tid = threadIdx.x;
    const int wid = tid >> 5;
    const int wm = wid >> 2, wn = wid & 3;
    const int bm = blockIdx.y, bn = blockIdx.x;

    wmma::fragment<wmma::accumulator, 16, 16, 16, float> acc[4][2];
#pragma unroll
    for (int i = 0; i < 4; i++)
#pragma unroll
        for (int j = 0; j < 2; j++) wmma::fill_fragment(acc[i][j], 0.f);

    const int r0 = tid >> 2;
    const int c0 = (tid & 3) * 8;
    const size_t aoff0 = (size_t)(bm * 128 + r0) * 2048 + c0;
    const size_t aoff1 = aoff0 + (size_t)64 * 2048;
    const size_t boff0 = (size_t)(bn * 128 + r0) * 2048 + c0;
    const size_t boff1 = boff0 + (size_t)64 * 2048;
    const int s0 = r0 * 40 + c0;
    const int s1 = (r0 + 64) * 40 + c0;

    float4 pA0, pA1, pBh0, pBh1, pBl0, pBl1;
    pA0  = *(const float4*)(A + aoff0);   pA1  = *(const float4*)(A + aoff1);
    pBh0 = *(const float4*)(Bhi + boff0); pBh1 = *(const float4*)(Bhi + boff1);
    pBl0 = *(const float4*)(Blo + boff0); pBl1 = *(const float4*)(Blo + boff1);
    *(float4*)(Ash + s0) = pA0;  *(float4*)(Ash + s1) = pA1;
    *(float4*)(Bsh + s0) = pBh0; *(float4*)(Bsh + s1) = pBh1;
    *(float4*)(Bsl + s0) = pBl0; *(float4*)(Bsl + s1) = pBl1;
    __syncthreads();

    for (int kt = 0; kt < 64; ++kt) {
        if (kt < 63) {
            const int kn = (kt + 1) * 32;
            pA0  = *(const float4*)(A + aoff0 + kn);   pA1  = *(const float4*)(A + aoff1 + kn);
            pBh0 = *(const float4*)(Bhi + boff0 + kn); pBh1 = *(const float4*)(Bhi + boff1 + kn);
            pBl0 = *(const float4*)(Blo + boff0 + kn); pBl1 = *(const float4*)(Blo + boff1 + kn);
        }
#pragma unroll
        for (int kk = 0; kk < 32; kk += 16) {
            wmma::fragment<wmma::matrix_a, 16, 16, 16, __half, wmma::row_major> af[4];
            wmma::fragment<wmma::matrix_b, 16, 16, 16, __half, wmma::col_major> bh[2], bl[2];
#pragma unroll
            for (int i = 0; i < 4; i++)
                wmma::load_matrix_sync(af[i], Ash + (wm * 64 + i * 16) * 40 + kk, 40);
#pragma unroll
            for (int j = 0; j < 2; j++) {
                wmma::load_matrix_sync(bh[j], Bsh + (wn * 32 + j * 16) * 40 + kk, 40);
                wmma::load_matrix_sync(bl[j], Bsl + (wn * 32 + j * 16) * 40 + kk, 40);
            }
#pragma unroll
            for (int i = 0; i < 4; i++)
#pragma unroll
                for (int j = 0; j < 2; j++) {
                    wmma::mma_sync(acc[i][j], af[i], bh[j], acc[i][j]);
                    wmma::mma_sync(acc[i][j], af[i], bl[j], acc[i][j]);
                }
        }
        __syncthreads();
        if (kt < 63) {
            *(float4*)(Ash + s0) = pA0;  *(float4*)(Ash + s1) = pA1;
            *(float4*)(Bsh + s0) = pBh0; *(float4*)(Bsh + s1) = pBh1;
            *(float4*)(Bsl + s0) = pBl0; *(float4*)(Bsl + s1) = pBl1;
        }
        __syncthreads();
    }

#pragma unroll
    for (int i = 0; i < 4; i++)
#pragma unroll
        for (int j = 0; j < 2; j++) {
            const int row = bm * 128 + wm * 64 + i * 16;
            const int col = bn * 128 + wn * 32 + j * 16;
            wmma::store_matrix_sync(Cg + (size_t)row * N + col, acc[i][j], N, wmma::mem_row_major);
        }
}

__global__ void __launch_bounds__(256) gemm_q_kernel()             { gemm_body(g_xq, g_Wq_hi, g_Wq_lo, g_Q, 2048); }
__global__ void __launch_bounds__(256) gemm_k_kernel()             { gemm_body(g_xk, g_Wk_hi, g_Wk_lo, g_K, 512); }
__global__ void __launch_bounds__(256) gemm_vinit_kernel(float* o) { gemm_body(g_x,  g_Wv_hi, g_Wv_lo, o, 512); }
__global__ void __launch_bounds__(256) gemm_cvx_kernel()           { gemm_body(g_xn, g_Wv_hi, g_Wv_lo, g_cvx, 512); }
__global__ void __launch_bounds__(256) gemm_proj_kernel(float* o)  { gemm_body(g_att, g_Wp_hi, g_Wp_lo, o, 2048); }

// ---------------------------------------------------------------------------
// RoPE + rmsnorm * 1.2, one warp per (b,t,head) row of 128
// ---------------------------------------------------------------------------
DEV_INLINE void rope_body(const float* __restrict__ inp, __half* __restrict__ outp,
                          const float* __restrict__ cosb, const float* __restrict__ sinb, int nh)
{
    const int wg = blockIdx.x * 8 + (threadIdx.x >> 5);
    const int lane = threadIdx.x & 31;
    const int t = (wg / nh) % T_;
    const size_t base = (size_t)wg * 128;

    float x1a = inp[base + lane];
    float x1b = inp[base + 32 + lane];
    float x2a = inp[base + 64 + lane];
    float x2b = inp[base + 96 + lane];
    float ca = cosb[t * 64 + lane], cb = cosb[t * 64 + 32 + lane];
    float sa = sinb[t * 64 + lane], sb = sinb[t * 64 + 32 + lane];

    float o1a =  x1a * ca + x2a * sa;
    float o1b =  x1b * cb + x2b * sb;
    float o2a = -x1a * sa + x2a * ca;
    float o2b = -x1b * sb + x2b * cb;

    float ssq = o1a*o1a + o1b*o1b + o2a*o2a + o2b*o2b;
#pragma unroll
    for (int o = 16; o > 0; o >>= 1) ssq += __shfl_xor_sync(0xffffffffu, ssq, o);
    float sc = rsqrtf(ssq / 128.f + EPS) * 1.2f;

    outp[base + lane]      = __float2half_rn(o1a * sc);
    outp[base + 32 + lane] = __float2half_rn(o1b * sc);
    outp[base + 64 + lane] = __float2half_rn(o2a * sc);
    outp[base + 96 + lane] = __float2half_rn(o2b * sc);
}
__global__ void __launch_bounds__(256) rope_q_kernel(const float* c, const float* s) { rope_body(g_Q, g_qa, c, s, H_); }
__global__ void __launch_bounds__(256) rope_k_kernel(const float* c, const float* s) { rope_body(g_K, g_ka, c, s, HK_); }

// ---------------------------------------------------------------------------
// v = alpha_v * v_init + beta_v * cvx
// ---------------------------------------------------------------------------
__global__ void __launch_bounds__(256) vcomb_kernel(const float* __restrict__ vinit,
                                                    const float* __restrict__ av,
                                                    const float* __restrict__ bv)
{
    int i = blockIdx.x * 256 + threadIdx.x;
    g_va[i] = __float2half_rn((*av) * vinit[i] + (*bv) * g_cvx[i]);
}

// ---------------------------------------------------------------------------
// Windowed causal flash attention, single fp16. CTA = 64 queries x one (b,h).
// 128 threads (4 warps). Dynamic smem 114688 B -> 2 CTAs/SM.
// ---------------------------------------------------------------------------
constexpr int ATT_SMEM = 114688;

__global__ void __launch_bounds__(128) attn_kernel()
{
    extern __shared__ char smraw[];
    __half* Qh = (__half*)(smraw);            // 64 x 136 fp16 = 17408
    __half* Kh = (__half*)(smraw + 17408);    // 17408
    __half* Vh = (__half*)(smraw + 34816);    // 17408
    float*  O  = (float*)(smraw + 52224);     // 64 x 136 fp32 = 34816
    float*  S  = (float*)(smraw + 87040);     // 64 x 72 fp32 = 18432
    __half* P  = (__half*)(smraw + 105472);   // 64 x 72 fp16 = 9216  (total 114688)

    const int tid = threadIdx.x;
    const int warp = tid >> 5;
    const int b = blockIdx.z, h = blockIdx.y;
    const int q0 = blockIdx.x * 64;
    const int hk = h >> 2;
    const int m0 = warp * 16;

    // load Q tile
#pragma unroll
    for (int tc = 0; tc < 4; ++tc) {
        int chunk = tid + tc * 128;
        int r = chunk >> 3;
        int c = (chunk & 7) * 16;
        size_t g = (size_t)(b * T_ + q0 + r) * 2048 + h * 128 + c;
        *(float4*)(Qh + r * 136 + c)     = *(const float4*)(g_qa + g);
        *(float4*)(Qh + r * 136 + c + 8) = *(const float4*)(g_qa + g + 8);
    }
    for (int i = tid; i < 64 * 136; i += 128) O[i] = 0.f;
    float m_r = -1e30f, l_r = 0.f;
    __syncthreads();

    const int kb0 = max(0, q0 - WIN_) >> 6;
    const int kb1 = q0 >> 6;
    for (int kb = kb0; kb <= kb1; ++kb) {
        const int k0 = kb * 64;
#pragma unroll
        for (int tc = 0; tc < 4; ++tc) {
            int chunk = tid + tc * 128;
            int r = chunk >> 3;
            int c = (chunk & 7) * 16;
            size_t g = (size_t)(b * T_ + k0 + r) * 512 + hk * 128 + c;
            *(float4*)(Kh + r * 136 + c)     = *(const float4*)(g_ka + g);
            *(float4*)(Kh + r * 136 + c + 8) = *(const float4*)(g_ka + g + 8);
            *(float4*)(Vh + r * 136 + c)     = *(const float4*)(g_va + g);
            *(float4*)(Vh + r * 136 + c + 8) = *(const float4*)(g_va + g + 8);
        }
        __syncthreads();

        // S = Q K^T
        wmma::fragment<wmma::accumulator, 16, 16, 16, float> sacc[4];
#pragma unroll
        for (int j = 0; j < 4; j++) wmma::fill_fragment(sacc[j], 0.f);
#pragma unroll
        for (int kk = 0; kk < 8; ++kk) {
            wmma::fragment<wmma::matrix_a, 16, 16, 16, __half, wmma::row_major> af;
            wmma::load_matrix_sync(af, Qh + m0 * 136 + kk * 16, 136);
#pragma unroll
            for (int j = 0; j < 4; j++) {
                wmma::fragment<wmma::matrix_b, 16, 16, 16, __half, wmma::col_major> bf;
                wmma::load_matrix_sync(bf, Kh + (j * 16) * 136 + kk * 16, 136);
                wmma::mma_sync(sacc[j], af, bf, sacc[j]);
            }
        }
#pragma unroll
        for (int j = 0; j < 4; j++)
            wmma::store_matrix_sync(S + m0 * 72 + j * 16, sacc[j], 72, wmma::mem_row_major);
        __syncthreads();

        // online softmax (thread r owns row r)
        if (tid < 64) {
            const int i_q = q0 + tid;
            float* Srow = S + tid * 72;
            float mx = -1e30f;
#pragma unroll 8
            for (int c = 0; c < 64; c++) {
                int j = k0 + c;
                float s = Srow[c] * ATT_SCALE;
                bool valid = (j <= i_q) && (i_q - j <= WIN_);
                s = valid ? s : -1e30f;
                Srow[c] = s;
                mx = fmaxf(mx, s);
            }
            float m_new = fmaxf(m_r, mx);
            float alpha = __expf(m_r - m_new);
            float lsum = 0.f;
            __half* Prow = P + tid * 72;
#pragma unroll 8
            for (int c = 0; c < 64; c++) {
                float p = __expf(Srow[c] - m_new);
                lsum += p;
                Prow[c] = __float2half_rn(p);
            }
            l_r = l_r * alpha + lsum;
            m_r = m_new;
            float* Orow = O + tid * 136;
#pragma unroll 8
            for (int c = 0; c < 128; c++) Orow[c] *= alpha;
        }
        __syncthreads();

        // O += P @ V
#pragma unroll
        for (int j = 0; j < 8; j++) {
            wmma::fragment<wmma::accumulator, 16, 16, 16, float> cfr;
            wmma::load_matrix_sync(cfr, O + m0 * 136 + j * 16, 136, wmma::mem_row_major);
#pragma unroll
            for (int kk = 0; kk < 4; kk++) {
                wmma::fragment<wmma::matrix_a, 16, 16, 16, __half, wmma::row_major> pa;
                wmma::load_matrix_sync(pa, P + m0 * 72 + kk * 16, 72);
                wmma::fragment<wmma::matrix_b, 16, 16, 16, __half, wmma::row_major> vb;
                wmma::load_matrix_sync(vb, Vh + (kk * 16) * 136 + j * 16, 136);
                wmma::mma_sync(cfr, pa, vb, cfr);
            }
            wmma::store_matrix_sync(O + m0 * 136 + j * 16, cfr, 136, wmma::mem_row_major);
        }
        __syncthreads();
    }

    // normalize + store attention output
    if (tid < 64) {
        const float inv_l = 1.f / l_r;
        float* Orow = O + tid * 136;
        size_t g = (size_t)(b * T_ + q0 + tid) * 2048 + h * 128;
        for (int c = 0; c < 128; c++)
            g_att[g + c] = __float2half_rn(Orow[c] * inv_l);
    }
}

// ---------------------------------------------------------------------------
// Launcher
// ---------------------------------------------------------------------------
extern "C" void kernel_launch(void* const* d_in, const int* in_sizes, int n_in,
                              void* d_out, int out_size)
{
    const float* x    = (const float*)d_in[0];
    const float* x0   = (const float*)d_in[1];
    // d_in[2] = ve : zeros, unused by reference
    const float* cosb = (const float*)d_in[3];
    const float* sinb = (const float*)d_in[4];
    const float* Wq   = (const float*)d_in[5];
    const float* Wk   = (const float*)d_in[6];
    const float* Wv   = (const float*)d_in[7];
    const float* Wp   = (const float*)d_in[8];
    const float* aq   = (const float*)d_in[9];
    const float* bq   = (const float*)d_in[10];
    const float* ak   = (const float*)d_in[11];
    const float* bk   = (const float*)d_in[12];
    const float* av   = (const float*)d_in[13];
    const float* bv   = (const float*)d_in[14];

    float* outY = (float*)d_out;                       // (B,T,C)
    float* outV = outY + (size_t)BT * C_;              // (B,T,HK,D)

    cudaFuncSetAttribute(attn_kernel, cudaFuncAttributeMaxDynamicSharedMemorySize, ATT_SMEM);

    conv_wq<<<(HD * C_) / 256, 256>>>(Wq);
    conv_wk<<<(HKD * C_) / 256, 256>>>(Wk);
    conv_wv<<<(HKD * C_) / 256, 256>>>(Wv);
    conv_wp<<<(C_ * HD) / 256, 256>>>(Wp);

    mix_kernel<<<BT, 256>>>(x, x0, aq, bq, ak, bk);

    gemm_q_kernel    <<<dim3(16, 64), 256>>>();
    gemm_k_kernel    <<<dim3(4, 64), 256>>>();
    gemm_vinit_kernel<<<dim3(4, 64), 256>>>(outV);
    gemm_cvx_kernel  <<<dim3(4, 64), 256>>>();

    rope_q_kernel<<<(BT * H_) / 8, 256>>>(cosb, sinb);
    rope_k_kernel<<<(BT * HK_) / 8, 256>>>(cosb, sinb);

    vcomb_kernel<<<(BT * HKD) / 256, 256>>>(outV, av, bv);

    attn_kernel<<<dim3(T_ / 64, H_, B_), 128, ATT_SMEM>>>();

    gemm_proj_kernel<<<dim3(16, 64), 256>>>(outY);
}

// round 7
// speedup vs baseline: 1.7582x; 1.1616x over previous
#include <cuda_runtime.h>
#include <cuda_fp16.h>
#include <cstdint>
#include <mma.h>

using namespace nvcuda;

#define DEV_INLINE __device__ __forceinline__

// Problem constants
constexpr int B_ = 4, T_ = 2048, C_ = 2048, H_ = 16, HK_ = 4, D_ = 128, WIN_ = 1024;
constexpr int BT  = B_ * T_;    // 8192
constexpr int HD  = H_ * D_;    // 2048
constexpr int HKD = HK_ * D_;   // 512
constexpr float EPS = 1.1920928955078125e-07f;
constexpr float ATT_SCALE = 0.08838834764831845f; // 1/sqrt(128)

DEV_INLINE uint32_t smem_u32(const void* p) {
    uint32_t a;
    asm("{ .reg .u64 t; cvta.to.shared.u64 t, %1; cvt.u32.u64 %0, t; }" : "=r"(a) : "l"(p));
    return a;
}
DEV_INLINE void cp16(uint32_t s, const void* g) {
    asm volatile("cp.async.cg.shared.global [%0], [%1], 16;" :: "r"(s), "l"(g) : "memory");
}
#define CP_COMMIT() asm volatile("cp.async.commit_group;" ::: "memory")
#define CP_WAIT1()  asm volatile("cp.async.wait_group 1;" ::: "memory")

// ---------------------------------------------------------------------------
// Scratch (device globals)
// ---------------------------------------------------------------------------
__device__ __half g_xq[BT * C_];
__device__ __half g_xk[BT * C_];
__device__ __half g_x [BT * C_];
__device__ __half g_xn[BT * C_];

__device__ __half g_Wq_hi[HD * C_],  g_Wq_lo[HD * C_];
__device__ __half g_Wk_hi[HKD * C_], g_Wk_lo[HKD * C_];
__device__ __half g_Wv_hi[HKD * C_], g_Wv_lo[HKD * C_];
__device__ __half g_Wp_hi[C_ * HD],  g_Wp_lo[C_ * HD];

__device__ float g_Q  [BT * HD];
__device__ float g_K  [BT * HKD];
__device__ float g_cvx[BT * HKD];

__device__ __half g_qa [BT * HD];
__device__ __half g_ka [BT * HKD];
__device__ __half g_va [BT * HKD];
__device__ __half g_att[BT * HD];

DEV_INLINE void split_store(float v, __half* hi, __half* lo, size_t idx) {
    __half h = __float2half_rn(v);
    hi[idx] = h;
    lo[idx] = __float2half_rn(v - __half2float(h));
}

// ---------------------------------------------------------------------------
// Weight fp32 -> (hi, lo) fp16 split
// ---------------------------------------------------------------------------
DEV_INLINE void conv_body(const float* __restrict__ w, __half* hi, __half* lo, int n) {
    int i = blockIdx.x * 256 + threadIdx.x;
    if (i < n) split_store(w[i], hi, lo, i);
}
__global__ void conv_wq(const float* __restrict__ w) { conv_body(w, g_Wq_hi, g_Wq_lo, HD * C_); }
__global__ void conv_wk(const float* __restrict__ w) { conv_body(w, g_Wk_hi, g_Wk_lo, HKD * C_); }
__global__ void conv_wv(const float* __restrict__ w) { conv_body(w, g_Wv_hi, g_Wv_lo, HKD * C_); }
__global__ void conv_wp(const float* __restrict__ w) { conv_body(w, g_Wp_hi, g_Wp_lo, C_ * HD); }

// ---------------------------------------------------------------------------
// Fused rmsnorm(x0) + linear mix, fp16 outputs
// ---------------------------------------------------------------------------
__global__ void __launch_bounds__(256) mix_kernel(
    const float* __restrict__ x, const float* __restrict__ x0,
    const float* __restrict__ aq, const float* __restrict__ bq,
    const float* __restrict__ ak, const float* __restrict__ bk)
{
    __shared__ float sred[8];
    const int row = blockIdx.x;
    const int tid = threadIdx.x;
    const size_t base = (size_t)row * C_;

    const float4* x0v = (const float4*)(x0 + base);
    const float4* xv  = (const float4*)(x + base);
    float4 u0 = x0v[tid], u1 = x0v[tid + 256];
    float ssq = u0.x*u0.x + u0.y*u0.y + u0.z*u0.z + u0.w*u0.w
              + u1.x*u1.x + u1.y*u1.y + u1.z*u1.z + u1.w*u1.w;
#pragma unroll
    for (int o = 16; o > 0; o >>= 1) ssq += __shfl_xor_sync(0xffffffffu, ssq, o);
    if ((tid & 31) == 0) sred[tid >> 5] = ssq;
    __syncthreads();
    float tot = 0.f;
#pragma unroll
    for (int i = 0; i < 8; i++) tot += sred[i];
    const float rinv = rsqrtf(tot / (float)C_ + EPS);

    const float aqv = *aq, bqv = *bq, akv = *ak, bkv = *bk;
    float4 v0 = xv[tid], v1 = xv[tid + 256];

    float xs[8]  = {v0.x, v0.y, v0.z, v0.w, v1.x, v1.y, v1.z, v1.w};
    float x0s[8] = {u0.x, u0.y, u0.z, u0.w, u1.x, u1.y, u1.z, u1.w};
#pragma unroll
    for (int c = 0; c < 8; c++) {
        size_t e = base + (size_t)((c < 4 ? tid : tid + 256) * 4 + (c & 3));
        float xvv = xs[c];
        float xnn = x0s[c] * rinv;
        g_x [e] = __float2half_rn(xvv);
        g_xn[e] = __float2half_rn(xnn);
        g_xq[e] = __float2half_rn(aqv * xvv + bqv * xnn);
        g_xk[e] = __float2half_rn(akv * xvv + bkv * xnn);
    }
}

// ---------------------------------------------------------------------------
// fp16 TN GEMM, cp.async 3-stage pipeline: C = A @ (Bhi + Blo)^T, fp32 out.
// Block tile 128x128x32, 8 warps (2x4), warp tile 64x32, 2 mma passes.
// smem stride 40 halves (80B): LDSM-conflict-free (80 mod 128 cycles all banks).
// ---------------------------------------------------------------------------
constexpr int GNS = 3;
constexpr int G_STAGE_B = 3 * 10240;          // A + Bh + Bl tiles (bytes)
constexpr int GEMM_SMEM = GNS * G_STAGE_B;    // 92160

DEV_INLINE void gemm_body(const __half* __restrict__ A,
                          const __half* __restrict__ Bhi, const __half* __restrict__ Blo,
                          float* __restrict__ Cg, int N)
{
    extern __shared__ char smem[];
    const uint32_t sbase = smem_u32(smem);
    const int tid = threadIdx.x;
    const int wid = tid >> 5;
    const int wm = wid >> 2, wn = wid & 3;
    const int bm = blockIdx.y, bn = blockIdx.x;

    wmma::fragment<wmma::accumulator, 16, 16, 16, float> acc[4][2];
#pragma unroll
    for (int i = 0; i < 4; i++)
#pragma unroll
        for (int j = 0; j < 2; j++) wmma::fill_fragment(acc[i][j], 0.f);

    const int r0 = tid >> 2;
    const int c0 = (tid & 3) * 8;
    const __half* Ap0 = A   + (size_t)(bm * 128 + r0) * 2048 + c0;
    const __half* Ap1 = Ap0 + (size_t)64 * 2048;
    const __half* Bh0 = Bhi + (size_t)(bn * 128 + r0) * 2048 + c0;
    const __half* Bh1 = Bh0 + (size_t)64 * 2048;
    const __half* Bl0 = Blo + (size_t)(bn * 128 + r0) * 2048 + c0;
    const __half* Bl1 = Bl0 + (size_t)64 * 2048;
    const uint32_t so0 = (uint32_t)(r0 * 40 + c0) * 2;
    const uint32_t so1 = (uint32_t)((r0 + 64) * 40 + c0) * 2;

    auto issue = [&](int stg, int kt) {
        const int kc = kt * 32;
        const uint32_t sb = sbase + stg * G_STAGE_B;
        cp16(sb + so0, Ap0 + kc);          cp16(sb + so1, Ap1 + kc);
        cp16(sb + 10240 + so0, Bh0 + kc);  cp16(sb + 10240 + so1, Bh1 + kc);
        cp16(sb + 20480 + so0, Bl0 + kc);  cp16(sb + 20480 + so1, Bl1 + kc);
    };

    issue(0, 0); CP_COMMIT();
    issue(1, 1); CP_COMMIT();

    for (int kt = 0; kt < 64; ++kt) {
        CP_WAIT1();
        __syncthreads();   // data of stage kt visible; prev compute done -> safe reuse
        const int nk = kt + 2;
        if (nk < 64) issue(nk % GNS, nk);
        CP_COMMIT();       // commit every iter (possibly empty) to keep counts aligned

        const __half* st  = (const __half*)(smem + (kt % GNS) * G_STAGE_B);
        const __half* Ash = st;
        const __half* Bsh = st + 5120;
        const __half* Bsl = st + 10240;
#pragma unroll
        for (int kk = 0; kk < 32; kk += 16) {
            wmma::fragment<wmma::matrix_a, 16, 16, 16, __half, wmma::row_major> af[4];
            wmma::fragment<wmma::matrix_b, 16, 16, 16, __half, wmma::col_major> bh[2], bl[2];
#pragma unroll
            for (int i = 0; i < 4; i++)
                wmma::load_matrix_sync(af[i], Ash + (wm * 64 + i * 16) * 40 + kk, 40);
#pragma unroll
            for (int j = 0; j < 2; j++) {
                wmma::load_matrix_sync(bh[j], Bsh + (wn * 32 + j * 16) * 40 + kk, 40);
                wmma::load_matrix_sync(bl[j], Bsl + (wn * 32 + j * 16) * 40 + kk, 40);
            }
#pragma unroll
            for (int i = 0; i < 4; i++)
#pragma unroll
                for (int j = 0; j < 2; j++) {
                    wmma::mma_sync(acc[i][j], af[i], bh[j], acc[i][j]);
                    wmma::mma_sync(acc[i][j], af[i], bl[j], acc[i][j]);
                }
        }
    }

#pragma unroll
    for (int i = 0; i < 4; i++)
#pragma unroll
        for (int j = 0; j < 2; j++) {
            const int row = bm * 128 + wm * 64 + i * 16;
            const int col = bn * 128 + wn * 32 + j * 16;
            wmma::store_matrix_sync(Cg + (size_t)row * N + col, acc[i][j], N, wmma::mem_row_major);
        }
}

__global__ void __launch_bounds__(256) gemm_q_kernel()             { gemm_body(g_xq, g_Wq_hi, g_Wq_lo, g_Q, 2048); }
__global__ void __launch_bounds__(256) gemm_k_kernel()             { gemm_body(g_xk, g_Wk_hi, g_Wk_lo, g_K, 512); }
__global__ void __launch_bounds__(256) gemm_vinit_kernel(float* o) { gemm_body(g_x,  g_Wv_hi, g_Wv_lo, o, 512); }
__global__ void __launch_bounds__(256) gemm_cvx_kernel()           { gemm_body(g_xn, g_Wv_hi, g_Wv_lo, g_cvx, 512); }
__global__ void __launch_bounds__(256) gemm_proj_kernel(float* o)  { gemm_body(g_att, g_Wp_hi, g_Wp_lo, o, 2048); }

// ---------------------------------------------------------------------------
// RoPE + rmsnorm * 1.2, one warp per (b,t,head) row of 128
// ---------------------------------------------------------------------------
DEV_INLINE void rope_body(const float* __restrict__ inp, __half* __restrict__ outp,
                          const float* __restrict__ cosb, const float* __restrict__ sinb, int nh)
{
    const int wg = blockIdx.x * 8 + (threadIdx.x >> 5);
    const int lane = threadIdx.x & 31;
    const int t = (wg / nh) % T_;
    const size_t base = (size_t)wg * 128;

    float x1a = inp[base + lane];
    float x1b = inp[base + 32 + lane];
    float x2a = inp[base + 64 + lane];
    float x2b = inp[base + 96 + lane];
    float ca = cosb[t * 64 + lane], cb = cosb[t * 64 + 32 + lane];
    float sa = sinb[t * 64 + lane], sb = sinb[t * 64 + 32 + lane];

    float o1a =  x1a * ca + x2a * sa;
    float o1b =  x1b * cb + x2b * sb;
    float o2a = -x1a * sa + x2a * ca;
    float o2b = -x1b * sb + x2b * cb;

    float ssq = o1a*o1a + o1b*o1b + o2a*o2a + o2b*o2b;
#pragma unroll
    for (int o = 16; o > 0; o >>= 1) ssq += __shfl_xor_sync(0xffffffffu, ssq, o);
    float sc = rsqrtf(ssq / 128.f + EPS) * 1.2f;

    outp[base + lane]      = __float2half_rn(o1a * sc);
    outp[base + 32 + lane] = __float2half_rn(o1b * sc);
    outp[base + 64 + lane] = __float2half_rn(o2a * sc);
    outp[base + 96 + lane] = __float2half_rn(o2b * sc);
}
__global__ void __launch_bounds__(256) rope_q_kernel(const float* c, const float* s) { rope_body(g_Q, g_qa, c, s, H_); }
__global__ void __launch_bounds__(256) rope_k_kernel(const float* c, const float* s) { rope_body(g_K, g_ka, c, s, HK_); }

// ---------------------------------------------------------------------------
// v = alpha_v * v_init + beta_v * cvx
// ---------------------------------------------------------------------------
__global__ void __launch_bounds__(256) vcomb_kernel(const float* __restrict__ vinit,
                                                    const float* __restrict__ av,
                                                    const float* __restrict__ bv)
{
    int i = blockIdx.x * 256 + threadIdx.x;
    g_va[i] = __float2half_rn((*av) * vinit[i] + (*bv) * g_cvx[i]);
}

// ---------------------------------------------------------------------------
// Windowed causal flash attention, fp16. 64 queries x one (b,h), 128 threads.
// Register prefetch of next K/V block; softmax parallelized 2 threads/row.
// Dynamic smem 114688 B -> 2 CTAs/SM.
// ---------------------------------------------------------------------------
constexpr int ATT_SMEM = 114688;

__global__ void __launch_bounds__(128) attn_kernel()
{
    extern __shared__ char smraw[];
    __half* Qh = (__half*)(smraw);            // 64 x 136
    __half* Kh = (__half*)(smraw + 17408);
    __half* Vh = (__half*)(smraw + 34816);
    float*  O  = (float*)(smraw + 52224);     // 64 x 136 fp32
    float*  S  = (float*)(smraw + 87040);     // 64 x 72 fp32
    __half* P  = (__half*)(smraw + 105472);   // 64 x 72 fp16

    const int tid = threadIdx.x;
    const int warp = tid >> 5;
    const int b = blockIdx.z, h = blockIdx.y;
    const int q0 = blockIdx.x * 64;
    const int hk = h >> 2;
    const int m0 = warp * 16;

    // load Q tile
#pragma unroll
    for (int tc = 0; tc < 4; ++tc) {
        int chunk = tid + tc * 128;
        int r = chunk >> 3;
        int c = (chunk & 7) * 16;
        size_t g = (size_t)(b * T_ + q0 + r) * 2048 + h * 128 + c;
        *(float4*)(Qh + r * 136 + c)     = *(const float4*)(g_qa + g);
        *(float4*)(Qh + r * 136 + c + 8) = *(const float4*)(g_qa + g + 8);
    }
    for (int i = tid; i < 64 * 136; i += 128) O[i] = 0.f;
    float m_r = -1e30f, l_r = 0.f;
    __syncthreads();

    const int kb0 = max(0, q0 - WIN_) >> 6;
    const int kb1 = q0 >> 6;

    float4 pk[8], pv[8];
    auto ld_kv = [&](int k0) {
#pragma unroll
        for (int tc = 0; tc < 4; ++tc) {
            int chunk = tid + tc * 128;
            int r = chunk >> 3;
            int c = (chunk & 7) * 16;
            size_t g = (size_t)(b * T_ + k0 + r) * 512 + hk * 128 + c;
            pk[tc * 2]     = *(const float4*)(g_ka + g);
            pk[tc * 2 + 1] = *(const float4*)(g_ka + g + 8);
            pv[tc * 2]     = *(const float4*)(g_va + g);
            pv[tc * 2 + 1] = *(const float4*)(g_va + g + 8);
        }
    };
    auto st_kv = [&]() {
#pragma unroll
        for (int tc = 0; tc < 4; ++tc) {
            int chunk = tid + tc * 128;
            int r = chunk >> 3;
            int c = (chunk & 7) * 16;
            *(float4*)(Kh + r * 136 + c)     = pk[tc * 2];
            *(float4*)(Kh + r * 136 + c + 8) = pk[tc * 2 + 1];
            *(float4*)(Vh + r * 136 + c)     = pv[tc * 2];
            *(float4*)(Vh + r * 136 + c + 8) = pv[tc * 2 + 1];
        }
    };

    ld_kv(kb0 * 64);
    for (int kb = kb0; kb <= kb1; ++kb) {
        const int k0 = kb * 64;
        st_kv();
        __syncthreads();
        if (kb < kb1) ld_kv((kb + 1) * 64);   // overlap next loads with compute

        // S = Q K^T
        wmma::fragment<wmma::accumulator, 16, 16, 16, float> sacc[4];
#pragma unroll
        for (int j = 0; j < 4; j++) wmma::fill_fragment(sacc[j], 0.f);
#pragma unroll
        for (int kk = 0; kk < 8; ++kk) {
            wmma::fragment<wmma::matrix_a, 16, 16, 16, __half, wmma::row_major> af;
            wmma::load_matrix_sync(af, Qh + m0 * 136 + kk * 16, 136);
#pragma unroll
            for (int j = 0; j < 4; j++) {
                wmma::fragment<wmma::matrix_b, 16, 16, 16, __half, wmma::col_major> bf;
                wmma::load_matrix_sync(bf, Kh + (j * 16) * 136 + kk * 16, 136);
                wmma::mma_sync(sacc[j], af, bf, sacc[j]);
            }
        }
#pragma unroll
        for (int j = 0; j < 4; j++)
            wmma::store_matrix_sync(S + m0 * 72 + j * 16, sacc[j], 72, wmma::mem_row_major);
        __syncthreads();

        // online softmax: 2 threads per row (shfl-combined)
        {
            const int row = tid >> 1, half = tid & 1;
            const int i_q = q0 + row;
            float* Srow = S + row * 72;
            const int cb = half * 32;
            float mx = -1e30f;
#pragma unroll 8
            for (int c = cb; c < cb + 32; c++) {
                int j = k0 + c;
                float s = Srow[c] * ATT_SCALE;
                bool valid = (j <= i_q) && (i_q - j <= WIN_);
                s = valid ? s : -1e30f;
                Srow[c] = s;
                mx = fmaxf(mx, s);
            }
            mx = fmaxf(mx, __shfl_xor_sync(0xffffffffu, mx, 1));
            float m_new = fmaxf(m_r, mx);
            float alpha = __expf(m_r - m_new);
            float lsum = 0.f;
            __half* Prow = P + row * 72;
#pragma unroll 8
            for (int c = cb; c < cb + 32; c++) {
                float p = __expf(Srow[c] - m_new);
                lsum += p;
                Prow[c] = __float2half_rn(p);
            }
            lsum += __shfl_xor_sync(0xffffffffu, lsum, 1);
            l_r = l_r * alpha + lsum;
            m_r = m_new;
            float* Orow = O + row * 136;
#pragma unroll 8
            for (int c = half * 64; c < half * 64 + 64; c++) Orow[c] *= alpha;
        }
        __syncthreads();

        // O += P @ V
#pragma unroll
        for (int j = 0; j < 8; j++) {
            wmma::fragment<wmma::accumulator, 16, 16, 16, float> cfr;
            wmma::load_matrix_sync(cfr, O + m0 * 136 + j * 16, 136, wmma::mem_row_major);
#pragma unroll
            for (int kk = 0; kk < 4; kk++) {
                wmma::fragment<wmma::matrix_a, 16, 16, 16, __half, wmma::row_major> pa;
                wmma::load_matrix_sync(pa, P + m0 * 72 + kk * 16, 72);
                wmma::fragment<wmma::matrix_b, 16, 16, 16, __half, wmma::row_major> vb;
                wmma::load_matrix_sync(vb, Vh + (kk * 16) * 136 + j * 16, 136);
                wmma::mma_sync(cfr, pa, vb, cfr);
            }
            wmma::store_matrix_sync(O + m0 * 136 + j * 16, cfr, 136, wmma::mem_row_major);
        }
        __syncthreads();
    }

    // normalize + store (2 threads per row)
    {
        const int row = tid >> 1, half = tid & 1;
        const float inv_l = 1.f / l_r;
        float* Orow = O + row * 136;
        size_t g = (size_t)(b * T_ + q0 + row) * 2048 + h * 128 + half * 64;
#pragma unroll 8
        for (int c = 0; c < 64; c++)
            g_att[g + c] = __float2half_rn(Orow[half * 64 + c] * inv_l);
    }
}

// ---------------------------------------------------------------------------
// Launcher
// ---------------------------------------------------------------------------
extern "C" void kernel_launch(void* const* d_in, const int* in_sizes, int n_in,
                              void* d_out, int out_size)
{
    const float* x    = (const float*)d_in[0];
    const float* x0   = (const float*)d_in[1];
    // d_in[2] = ve : zeros, unused by reference
    const float* cosb = (const float*)d_in[3];
    const float* sinb = (const float*)d_in[4];
    const float* Wq   = (const float*)d_in[5];
    const float* Wk   = (const float*)d_in[6];
    const float* Wv   = (const float*)d_in[7];
    const float* Wp   = (const float*)d_in[8];
    const float* aq   = (const float*)d_in[9];
    const float* bq   = (const float*)d_in[10];
    const float* ak   = (const float*)d_in[11];
    const float* bk   = (const float*)d_in[12];
    const float* av   = (const float*)d_in[13];
    const float* bv   = (const float*)d_in[14];

    float* outY = (float*)d_out;                       // (B,T,C)
    float* outV = outY + (size_t)BT * C_;              // (B,T,HK,D)

    cudaFuncSetAttribute(attn_kernel,       cudaFuncAttributeMaxDynamicSharedMemorySize, ATT_SMEM);
    cudaFuncSetAttribute(gemm_q_kernel,     cudaFuncAttributeMaxDynamicSharedMemorySize, GEMM_SMEM);
    cudaFuncSetAttribute(gemm_k_kernel,     cudaFuncAttributeMaxDynamicSharedMemorySize, GEMM_SMEM);
    cudaFuncSetAttribute(gemm_vinit_kernel, cudaFuncAttributeMaxDynamicSharedMemorySize, GEMM_SMEM);
    cudaFuncSetAttribute(gemm_cvx_kernel,   cudaFuncAttributeMaxDynamicSharedMemorySize, GEMM_SMEM);
    cudaFuncSetAttribute(gemm_proj_kernel,  cudaFuncAttributeMaxDynamicSharedMemorySize, GEMM_SMEM);

    conv_wq<<<(HD * C_) / 256, 256>>>(Wq);
    conv_wk<<<(HKD * C_) / 256, 256>>>(Wk);
    conv_wv<<<(HKD * C_) / 256, 256>>>(Wv);
    conv_wp<<<(C_ * HD) / 256, 256>>>(Wp);

    mix_kernel<<<BT, 256>>>(x, x0, aq, bq, ak, bk);

    gemm_q_kernel    <<<dim3(16, 64), 256, GEMM_SMEM>>>();
    gemm_k_kernel    <<<dim3(4, 64),  256, GEMM_SMEM>>>();
    gemm_vinit_kernel<<<dim3(4, 64),  256, GEMM_SMEM>>>(outV);
    gemm_cvx_kernel  <<<dim3(4, 64),  256, GEMM_SMEM>>>();

    rope_q_kernel<<<(BT * H_) / 8, 256>>>(cosb, sinb);
    rope_k_kernel<<<(BT * HK_) / 8, 256>>>(cosb, sinb);

    vcomb_kernel<<<(BT * HKD) / 256, 256>>>(outV, av, bv);

    attn_kernel<<<dim3(T_ / 64, H_, B_), 128, ATT_SMEM>>>();

    gemm_proj_kernel<<<dim3(16, 64), 256, GEMM_SMEM>>>(outY);
}

// round 9
// speedup vs baseline: 2.1620x; 1.2297x over previous
#include <cuda_runtime.h>
#include <cuda_fp16.h>
#include <cstdint>
#include <mma.h>

using namespace nvcuda;

#define DEV_INLINE __device__ __forceinline__

// Problem constants
constexpr int B_ = 4, T_ = 2048, C_ = 2048, H_ = 16, HK_ = 4, D_ = 128, WIN_ = 1024;
constexpr int BT  = B_ * T_;    // 8192
constexpr int HD  = H_ * D_;    // 2048
constexpr int HKD = HK_ * D_;   // 512
constexpr float EPS = 1.1920928955078125e-07f;
constexpr float ATT_SCALE = 0.08838834764831845f; // 1/sqrt(128)

DEV_INLINE uint32_t smem_u32(const void* p) {
    uint32_t a;
    asm("{ .reg .u64 t; cvta.to.shared.u64 t, %1; cvt.u32.u64 %0, t; }" : "=r"(a) : "l"(p));
    return a;
}
DEV_INLINE void cp16(uint32_t s, const void* g) {
    asm volatile("cp.async.cg.shared.global [%0], [%1], 16;" :: "r"(s), "l"(g) : "memory");
}
#define CP_COMMIT() asm volatile("cp.async.commit_group;" ::: "memory")
#define CP_WAIT1()  asm volatile("cp.async.wait_group 1;" ::: "memory")
#define CP_WAIT2()  asm volatile("cp.async.wait_group 2;" ::: "memory")

// ---------------------------------------------------------------------------
// Scratch (device globals)
// ---------------------------------------------------------------------------
__device__ __half g_xq[BT * C_];
__device__ __half g_xk[BT * C_];
__device__ __half g_x [BT * C_];
__device__ __half g_xn[BT * C_];

__device__ __half g_Wq[HD * C_];               // 1-pass weights
__device__ __half g_Wk[HKD * C_];
__device__ __half g_Wp[C_ * HD];
__device__ __half g_Wv_hi[HKD * C_], g_Wv_lo[HKD * C_];   // 2-pass (v path)

__device__ float g_Q  [BT * HD];
__device__ float g_K  [BT * HKD];
__device__ float g_cvx[BT * HKD];

__device__ __half g_qa [BT * HD];
__device__ __half g_ka [BT * HKD];
__device__ __half g_va [BT * HKD];
__device__ __half g_att[BT * HD];

// ---------------------------------------------------------------------------
// Weight conversions
// ---------------------------------------------------------------------------
DEV_INLINE void conv_hi_body(const float* __restrict__ w, __half* o, int n) {
    int i = blockIdx.x * 256 + threadIdx.x;
    if (i < n) o[i] = __float2half_rn(w[i]);
}
__global__ void conv_wq(const float* __restrict__ w) { conv_hi_body(w, g_Wq, HD * C_); }
__global__ void conv_wk(const float* __restrict__ w) { conv_hi_body(w, g_Wk, HKD * C_); }
__global__ void conv_wp(const float* __restrict__ w) { conv_hi_body(w, g_Wp, C_ * HD); }
__global__ void conv_wv(const float* __restrict__ w) {
    int i = blockIdx.x * 256 + threadIdx.x;
    if (i < HKD * C_) {
        float v = w[i];
        __half h = __float2half_rn(v);
        g_Wv_hi[i] = h;
        g_Wv_lo[i] = __float2half_rn(v - __half2float(h));
    }
}

// ---------------------------------------------------------------------------
// Fused rmsnorm(x0) + linear mix, fp16 outputs
// ---------------------------------------------------------------------------
__global__ void __launch_bounds__(256) mix_kernel(
    const float* __restrict__ x, const float* __restrict__ x0,
    const float* __restrict__ aq, const float* __restrict__ bq,
    const float* __restrict__ ak, const float* __restrict__ bk)
{
    __shared__ float sred[8];
    const int row = blockIdx.x;
    const int tid = threadIdx.x;
    const size_t base = (size_t)row * C_;

    const float4* x0v = (const float4*)(x0 + base);
    const float4* xv  = (const float4*)(x + base);
    float4 u0 = x0v[tid], u1 = x0v[tid + 256];
    float ssq = u0.x*u0.x + u0.y*u0.y + u0.z*u0.z + u0.w*u0.w
              + u1.x*u1.x + u1.y*u1.y + u1.z*u1.z + u1.w*u1.w;
#pragma unroll
    for (int o = 16; o > 0; o >>= 1) ssq += __shfl_xor_sync(0xffffffffu, ssq, o);
    if ((tid & 31) == 0) sred[tid >> 5] = ssq;
    __syncthreads();
    float tot = 0.f;
#pragma unroll
    for (int i = 0; i < 8; i++) tot += sred[i];
    const float rinv = rsqrtf(tot / (float)C_ + EPS);

    const float aqv = *aq, bqv = *bq, akv = *ak, bkv = *bk;
    float4 v0 = xv[tid], v1 = xv[tid + 256];

    float xs[8]  = {v0.x, v0.y, v0.z, v0.w, v1.x, v1.y, v1.z, v1.w};
    float x0s[8] = {u0.x, u0.y, u0.z, u0.w, u1.x, u1.y, u1.z, u1.w};
#pragma unroll
    for (int c = 0; c < 8; c++) {
        size_t e = base + (size_t)((c < 4 ? tid : tid + 256) * 4 + (c & 3));
        float xvv = xs[c];
        float xnn = x0s[c] * rinv;
        g_x [e] = __float2half_rn(xvv);
        g_xn[e] = __float2half_rn(xnn);
        g_xq[e] = __float2half_rn(aqv * xvv + bqv * xnn);
        g_xk[e] = __float2half_rn(akv * xvv + bkv * xnn);
    }
}

// ---------------------------------------------------------------------------
// fp16 TN GEMM, cp.async pipeline. PASSES=1: C = A @ B^T (4 stages, depth-3).
// PASSES=2: C = A @ (Bhi+Blo)^T (3 stages, depth-2).
// Block tile 128x128x32, 8 warps (2x4), warp tile 64x32.
// smem stride 40 halves (80B): LDSM-conflict-free.
// ---------------------------------------------------------------------------
constexpr int TILE_B = 10240;  // one operand tile (128 x 40 halves) in bytes

template <int PASSES>
DEV_INLINE void gemm_core(const __half* __restrict__ A,
                          const __half* __restrict__ Bhi, const __half* __restrict__ Blo,
                          float* __restrict__ Cg, int N)
{
    constexpr int NST = (PASSES == 1) ? 4 : 3;
    constexpr int DEPTH = NST - 1;
    constexpr int STB = (PASSES + 1) * TILE_B;   // stage bytes

    extern __shared__ char smem[];
    const uint32_t sbase = smem_u32(smem);
    const int tid = threadIdx.x;
    const int wid = tid >> 5;
    const int wm = wid >> 2, wn = wid & 3;
    const int bm = blockIdx.y, bn = blockIdx.x;

    wmma::fragment<wmma::accumulator, 16, 16, 16, float> acc[4][2];
#pragma unroll
    for (int i = 0; i < 4; i++)
#pragma unroll
        for (int j = 0; j < 2; j++) wmma::fill_fragment(acc[i][j], 0.f);

    const int r0 = tid >> 2;
    const int c0 = (tid & 3) * 8;
    const __half* Ap0 = A   + (size_t)(bm * 128 + r0) * 2048 + c0;
    const __half* Ap1 = Ap0 + (size_t)64 * 2048;
    const __half* Bh0 = Bhi + (size_t)(bn * 128 + r0) * 2048 + c0;
    const __half* Bh1 = Bh0 + (size_t)64 * 2048;
    const __half* Bl0 = (PASSES == 2) ? (Blo + (size_t)(bn * 128 + r0) * 2048 + c0) : nullptr;
    const __half* Bl1 = (PASSES == 2) ? (Bl0 + (size_t)64 * 2048) : nullptr;
    const uint32_t so0 = (uint32_t)(r0 * 40 + c0) * 2;
    const uint32_t so1 = (uint32_t)((r0 + 64) * 40 + c0) * 2;

    auto issue = [&](int stg, int kt) {
        const int kc = kt * 32;
        const uint32_t sb = sbase + stg * STB;
        cp16(sb + so0, Ap0 + kc);           cp16(sb + so1, Ap1 + kc);
        cp16(sb + TILE_B + so0, Bh0 + kc);  cp16(sb + TILE_B + so1, Bh1 + kc);
        if (PASSES == 2) {
            cp16(sb + 2 * TILE_B + so0, Bl0 + kc);
            cp16(sb + 2 * TILE_B + so1, Bl1 + kc);
        }
    };

#pragma unroll
    for (int d = 0; d < DEPTH; ++d) { issue(d, d); CP_COMMIT(); }

    for (int kt = 0; kt < 64; ++kt) {
        if (PASSES == 1) { CP_WAIT2(); } else { CP_WAIT1(); }
        __syncthreads();
        const int nk = kt + DEPTH;
        if (nk < 64) issue(nk % NST, nk);
        CP_COMMIT();

        const __half* st  = (const __half*)(smem + (kt % NST) * STB);
        const __half* Ash = st;
        const __half* Bsh = st + 5120;
        const __half* Bsl = st + 10240;
#pragma unroll
        for (int kk = 0; kk < 32; kk += 16) {
            wmma::fragment<wmma::matrix_a, 16, 16, 16, __half, wmma::row_major> af[4];
            wmma::fragment<wmma::matrix_b, 16, 16, 16, __half, wmma::col_major> bh[2];
#pragma unroll
            for (int i = 0; i < 4; i++)
                wmma::load_matrix_sync(af[i], Ash + (wm * 64 + i * 16) * 40 + kk, 40);
#pragma unroll
            for (int j = 0; j < 2; j++)
                wmma::load_matrix_sync(bh[j], Bsh + (wn * 32 + j * 16) * 40 + kk, 40);
            if (PASSES == 2) {
                wmma::fragment<wmma::matrix_b, 16, 16, 16, __half, wmma::col_major> bl[2];
#pragma unroll
                for (int j = 0; j < 2; j++)
                    wmma::load_matrix_sync(bl[j], Bsl + (wn * 32 + j * 16) * 40 + kk, 40);
#pragma unroll
                for (int i = 0; i < 4; i++)
#pragma unroll
                    for (int j = 0; j < 2; j++) {
                        wmma::mma_sync(acc[i][j], af[i], bh[j], acc[i][j]);
                        wmma::mma_sync(acc[i][j], af[i], bl[j], acc[i][j]);
                    }
            } else {
#pragma unroll
                for (int i = 0; i < 4; i++)
#pragma unroll
                    for (int j = 0; j < 2; j++)
                        wmma::mma_sync(acc[i][j], af[i], bh[j], acc[i][j]);
            }
        }
    }

#pragma unroll
    for (int i = 0; i < 4; i++)
#pragma unroll
        for (int j = 0; j < 2; j++) {
            const int row = bm * 128 + wm * 64 + i * 16;
            const int col = bn * 128 + wn * 32 + j * 16;
            wmma::store_matrix_sync(Cg + (size_t)row * N + col, acc[i][j], N, wmma::mem_row_major);
        }
}

constexpr int GEMM_SMEM1 = 4 * 2 * TILE_B;  // 81920
constexpr int GEMM_SMEM2 = 3 * 3 * TILE_B;  // 92160

__global__ void __launch_bounds__(256) gemm_q_kernel()            { gemm_core<1>(g_xq, g_Wq, nullptr, g_Q, 2048); }
__global__ void __launch_bounds__(256) gemm_k_kernel()            { gemm_core<1>(g_xk, g_Wk, nullptr, g_K, 512); }
__global__ void __launch_bounds__(256) gemm_proj_kernel(float* o) { gemm_core<1>(g_att, g_Wp, nullptr, o, 2048); }
// z-batched: z=0 -> v_init = x @ Wv^T (to outV), z=1 -> cvx = xn @ Wv^T
__global__ void __launch_bounds__(256) gemm_v2_kernel(float* outV) {
    if (blockIdx.z == 0) gemm_core<2>(g_x,  g_Wv_hi, g_Wv_lo, outV,  512);
    else                 gemm_core<2>(g_xn, g_Wv_hi, g_Wv_lo, g_cvx, 512);
}

// ---------------------------------------------------------------------------
// RoPE + rmsnorm * 1.2, one warp per (b,t,head) row of 128
// ---------------------------------------------------------------------------
DEV_INLINE void rope_body(const float* __restrict__ inp, __half* __restrict__ outp,
                          const float* __restrict__ cosb, const float* __restrict__ sinb, int nh)
{
    const int wg = blockIdx.x * 8 + (threadIdx.x >> 5);
    const int lane = threadIdx.x & 31;
    const int t = (wg / nh) % T_;
    const size_t base = (size_t)wg * 128;

    float x1a = inp[base + lane];
    float x1b = inp[base + 32 + lane];
    float x2a = inp[base + 64 + lane];
    float x2b = inp[base + 96 + lane];
    float ca = cosb[t * 64 + lane], cb = cosb[t * 64 + 32 + lane];
    float sa = sinb[t * 64 + lane], sb = sinb[t * 64 + 32 + lane];

    float o1a =  x1a * ca + x2a * sa;
    float o1b =  x1b * cb + x2b * sb;
    float o2a = -x1a * sa + x2a * ca;
    float o2b = -x1b * sb + x2b * cb;

    float ssq = o1a*o1a + o1b*o1b + o2a*o2a + o2b*o2b;
#pragma unroll
    for (int o = 16; o > 0; o >>= 1) ssq += __shfl_xor_sync(0xffffffffu, ssq, o);
    float sc = rsqrtf(ssq / 128.f + EPS) * 1.2f;

    outp[base + lane]      = __float2half_rn(o1a * sc);
    outp[base + 32 + lane] = __float2half_rn(o1b * sc);
    outp[base + 64 + lane] = __float2half_rn(o2a * sc);
    outp[base + 96 + lane] = __float2half_rn(o2b * sc);
}
__global__ void __launch_bounds__(256) rope_q_kernel(const float* c, const float* s) { rope_body(g_Q, g_qa, c, s, H_); }
__global__ void __launch_bounds__(256) rope_k_kernel(const float* c, const float* s) { rope_body(g_K, g_ka, c, s, HK_); }

// ---------------------------------------------------------------------------
// v = alpha_v * v_init + beta_v * cvx
// ---------------------------------------------------------------------------
__global__ void __launch_bounds__(256) vcomb_kernel(const float* __restrict__ vinit,
                                                    const float* __restrict__ av,
                                                    const float* __restrict__ bv)
{
    int i = blockIdx.x * 256 + threadIdx.x;
    g_va[i] = __float2half_rn((*av) * vinit[i] + (*bv) * g_cvx[i]);
}

// ---------------------------------------------------------------------------
// Windowed causal flash attention, fp16. 64 queries x one (b,h), 128 threads.
// Register prefetch of next K/V block; softmax 2 threads/row.
// Dynamic smem 114688 B -> 2 CTAs/SM.
// ---------------------------------------------------------------------------
constexpr int ATT_SMEM = 114688;

__global__ void __launch_bounds__(128) attn_kernel()
{
    extern __shared__ char smraw[];
    __half* Qh = (__half*)(smraw);            // 64 x 136
    __half* Kh = (__half*)(smraw + 17408);
    __half* Vh = (__half*)(smraw + 34816);
    float*  O  = (float*)(smraw + 52224);     // 64 x 136 fp32
    float*  S  = (float*)(smraw + 87040);     // 64 x 72 fp32
    __half* P  = (__half*)(smraw + 105472);   // 64 x 72 fp16

    const int tid = threadIdx.x;
    const int warp = tid >> 5;
    const int b = blockIdx.z, h = blockIdx.y;
    const int q0 = blockIdx.x * 64;
    const int hk = h >> 2;
    const int m0 = warp * 16;

#pragma unroll
    for (int tc = 0; tc < 4; ++tc) {
        int chunk = tid + tc * 128;
        int r = chunk >> 3;
        int c = (chunk & 7) * 16;
        size_t g = (size_t)(b * T_ + q0 + r) * 2048 + h * 128 + c;
        *(float4*)(Qh + r * 136 + c)     = *(const float4*)(g_qa + g);
        *(float4*)(Qh + r * 136 + c + 8) = *(const float4*)(g_qa + g + 8);
    }
    for (int i = tid; i < 64 * 136; i += 128) O[i] = 0.f;
    float m_r = -1e30f, l_r = 0.f;
    __syncthreads();

    const int kb0 = max(0, q0 - WIN_) >> 6;
    const int kb1 = q0 >> 6;

    float4 pk[8], pv[8];
    auto ld_kv = [&](int k0) {
#pragma unroll
        for (int tc = 0; tc < 4; ++tc) {
            int chunk = tid + tc * 128;
            int r = chunk >> 3;
            int c = (chunk & 7) * 16;
            size_t g = (size_t)(b * T_ + k0 + r) * 512 + hk * 128 + c;
            pk[tc * 2]     = *(const float4*)(g_ka + g);
            pk[tc * 2 + 1] = *(const float4*)(g_ka + g + 8);
            pv[tc * 2]     = *(const float4*)(g_va + g);
            pv[tc * 2 + 1] = *(const float4*)(g_va + g + 8);
        }
    };
    auto st_kv = [&]() {
#pragma unroll
        for (int tc = 0; tc < 4; ++tc) {
            int chunk = tid + tc * 128;
            int r = chunk >> 3;
            int c = (chunk & 7) * 16;
            *(float4*)(Kh + r * 136 + c)     = pk[tc * 2];
            *(float4*)(Kh + r * 136 + c + 8) = pk[tc * 2 + 1];
            *(float4*)(Vh + r * 136 + c)     = pv[tc * 2];
            *(float4*)(Vh + r * 136 + c + 8) = pv[tc * 2 + 1];
        }
    };

    ld_kv(kb0 * 64);
    for (int kb = kb0; kb <= kb1; ++kb) {
        const int k0 = kb * 64;
        st_kv();
        __syncthreads();
        if (kb < kb1) ld_kv((kb + 1) * 64);

        // S = Q K^T
        wmma::fragment<wmma::accumulator, 16, 16, 16, float> sacc[4];
#pragma unroll
        for (int j = 0; j < 4; j++) wmma::fill_fragment(sacc[j], 0.f);
#pragma unroll
        for (int kk = 0; kk < 8; ++kk) {
            wmma::fragment<wmma::matrix_a, 16, 16, 16, __half, wmma::row_major> af;
            wmma::load_matrix_sync(af, Qh + m0 * 136 + kk * 16, 136);
#pragma unroll
            for (int j = 0; j < 4; j++) {
                wmma::fragment<wmma::matrix_b, 16, 16, 16, __half, wmma::col_major> bf;
                wmma::load_matrix_sync(bf, Kh + (j * 16) * 136 + kk * 16, 136);
                wmma::mma_sync(sacc[j], af, bf, sacc[j]);
            }
        }
#pragma unroll
        for (int j = 0; j < 4; j++)
            wmma::store_matrix_sync(S + m0 * 72 + j * 16, sacc[j], 72, wmma::mem_row_major);
        __syncthreads();

        // online softmax: 2 threads per row
        {
            const int row = tid >> 1, half = tid & 1;
            const int i_q = q0 + row;
            float* Srow = S + row * 72;
            const int cb = half * 32;
            float mx = -1e30f;
#pragma unroll 8
            for (int c = cb; c < cb + 32; c++) {
                int j = k0 + c;
                float s = Srow[c] * ATT_SCALE;
                bool valid = (j <= i_q) && (i_q - j <= WIN_);
                s = valid ? s : -1e30f;
                Srow[c] = s;
                mx = fmaxf(mx, s);
            }
            mx = fmaxf(mx, __shfl_xor_sync(0xffffffffu, mx, 1));
            float m_new = fmaxf(m_r, mx);
            float alpha = __expf(m_r - m_new);
            float lsum = 0.f;
            __half* Prow = P + row * 72;
#pragma unroll 8
            for (int c = cb; c < cb + 32; c++) {
                float p = __expf(Srow[c] - m_new);
                lsum += p;
                Prow[c] = __float2half_rn(p);
            }
            lsum += __shfl_xor_sync(0xffffffffu, lsum, 1);
            l_r = l_r * alpha + lsum;
            m_r = m_new;
            float* Orow = O + row * 136;
#pragma unroll 8
            for (int c = half * 64; c < half * 64 + 64; c++) Orow[c] *= alpha;
        }
        __syncthreads();

        // O += P @ V
#pragma unroll
        for (int j = 0; j < 8; j++) {
            wmma::fragment<wmma::accumulator, 16, 16, 16, float> cfr;
            wmma::load_matrix_sync(cfr, O + m0 * 136 + j * 16, 136, wmma::mem_row_major);
#pragma unroll
            for (int kk = 0; kk < 4; kk++) {
                wmma::fragment<wmma::matrix_a, 16, 16, 16, __half, wmma::row_major> pa;
                wmma::load_matrix_sync(pa, P + m0 * 72 + kk * 16, 72);
                wmma::fragment<wmma::matrix_b, 16, 16, 16, __half, wmma::row_major> vb;
                wmma::load_matrix_sync(vb, Vh + (kk * 16) * 136 + j * 16, 136);
                wmma::mma_sync(cfr, pa, vb, cfr);
            }
            wmma::store_matrix_sync(O + m0 * 136 + j * 16, cfr, 136, wmma::mem_row_major);
        }
        __syncthreads();
    }

    {
        const int row = tid >> 1, half = tid & 1;
        const float inv_l = 1.f / l_r;
        float* Orow = O + row * 136;
        size_t g = (size_t)(b * T_ + q0 + row) * 2048 + h * 128 + half * 64;
#pragma unroll 8
        for (int c = 0; c < 64; c++)
            g_att[g + c] = __float2half_rn(Orow[half * 64 + c] * inv_l);
    }
}

// ---------------------------------------------------------------------------
// Launcher
// ---------------------------------------------------------------------------
extern "C" void kernel_launch(void* const* d_in, const int* in_sizes, int n_in,
                              void* d_out, int out_size)
{
    const float* x    = (const float*)d_in[0];
    const float* x0   = (const float*)d_in[1];
    // d_in[2] = ve : zeros, unused by reference
    const float* cosb = (const float*)d_in[3];
    const float* sinb = (const float*)d_in[4];
    const float* Wq   = (const float*)d_in[5];
    const float* Wk   = (const float*)d_in[6];
    const float* Wv   = (const float*)d_in[7];
    const float* Wp   = (const float*)d_in[8];
    const float* aq   = (const float*)d_in[9];
    const float* bq   = (const float*)d_in[10];
    const float* ak   = (const float*)d_in[11];
    const float* bk   = (const float*)d_in[12];
    const float* av   = (const float*)d_in[13];
    const float* bv   = (const float*)d_in[14];

    float* outY = (float*)d_out;                       // (B,T,C)
    float* outV = outY + (size_t)BT * C_;              // (B,T,HK,D)

    cudaFuncSetAttribute(attn_kernel,      cudaFuncAttributeMaxDynamicSharedMemorySize, ATT_SMEM);
    cudaFuncSetAttribute(gemm_q_kernel,    cudaFuncAttributeMaxDynamicSharedMemorySize, GEMM_SMEM1);
    cudaFuncSetAttribute(gemm_k_kernel,    cudaFuncAttributeMaxDynamicSharedMemorySize, GEMM_SMEM1);
    cudaFuncSetAttribute(gemm_proj_kernel, cudaFuncAttributeMaxDynamicSharedMemorySize, GEMM_SMEM1);
    cudaFuncSetAttribute(gemm_v2_kernel,   cudaFuncAttributeMaxDynamicSharedMemorySize, GEMM_SMEM2);

    conv_wq<<<(HD * C_) / 256, 256>>>(Wq);
    conv_wk<<<(HKD * C_) / 256, 256>>>(Wk);
    conv_wv<<<(HKD * C_) / 256, 256>>>(Wv);
    conv_wp<<<(C_ * HD) / 256, 256>>>(Wp);

    mix_kernel<<<BT, 256>>>(x, x0, aq, bq, ak, bk);

    gemm_q_kernel <<<dim3(16, 64),    256, GEMM_SMEM1>>>();
    gemm_k_kernel <<<dim3(4, 64),     256, GEMM_SMEM1>>>();
    gemm_v2_kernel<<<dim3(4, 64, 2),  256, GEMM_SMEM2>>>(outV);

    rope_q_kernel<<<(BT * H_) / 8, 256>>>(cosb, sinb);
    rope_k_kernel<<<(BT * HK_) / 8, 256>>>(cosb, sinb);

    vcomb_kernel<<<(BT * HKD) / 256, 256>>>(outV, av, bv);

    attn_kernel<<<dim3(T_ / 64, H_, B_), 128, ATT_SMEM>>>();

    gemm_proj_kernel<<<dim3(16, 64), 256, GEMM_SMEM1>>>(outY);
}